// round 14
// baseline (speedup 1.0000x reference)
#include <cuda_runtime.h>
#include <cuda_bf16.h>

#define NN    1500
#define NEDGE 24000
#define EDIM  64
#define LOOPN 10
#define EB2   375            // NEDGE/64 edge tiles
#define NT2   24             // ceil(NN/64) node tiles

// ---------------- device scratch ----------------
__device__ float g_vc[NN * 8];
__device__ float g_goal[8];
__device__ float g_x[NN * EDIM];
__device__ float g_y[NEDGE * EDIM];
__device__ float g_msg[NEDGE * EDIM];
__device__ float g_Pf[NN * EDIM], g_Qf[NN * EDIM];
__device__ float g_Py[NN * EDIM], g_Qy[NN * EDIM];
__device__ float g_A1[EDIM * EDIM], g_B1[EDIM * EDIM];
__device__ float g_A2[EDIM * EDIM], g_B2[EDIM * EDIM];
__device__ float g_Ay[8 * EDIM],   g_By[8 * EDIM];
__device__ int   g_rowptr[NN + 1];
__device__ int   g_cols[NEDGE];
__device__ int   g_winner[NN * NN];

#define NEG_INF __int_as_float(0xff800000)

#define FMA8(acc, v, w0, w1)                                   \
    {   acc[0] += (v) * (w0).x; acc[1] += (v) * (w0).y;        \
        acc[2] += (v) * (w0).z; acc[3] += (v) * (w0).w;        \
        acc[4] += (v) * (w1).x; acc[5] += (v) * (w1).y;        \
        acc[6] += (v) * (w1).z; acc[7] += (v) * (w1).w; }

// tf32 convert (round-to-nearest)
__device__ __forceinline__ unsigned tf32c(float x) {
    unsigned u;
    asm("cvt.rna.tf32.f32 %0, %1;" : "=r"(u) : "f"(x));
    return u;
}

#define MMA_TF32(d0, d1, d2, d3, a0, a1, a2, a3, b0, b1)                    \
    asm volatile("mma.sync.aligned.m16n8k8.row.col.f32.tf32.tf32.f32 "      \
                 "{%0,%1,%2,%3}, {%4,%5,%6,%7}, {%8,%9}, {%0,%1,%2,%3};"    \
                 : "+f"(d0), "+f"(d1), "+f"(d2), "+f"(d3)                   \
                 : "r"(a0), "r"(a1), "r"(a2), "r"(a3), "r"(b0), "r"(b1))

// smem (floats)
#define AST 68
#define FX_SM  (4096 + 4096 + 64 * AST)       // Wy, W2, act (reused ys->hs) = 50 KB
#define EYA_SM (4096 + 4096 + 4160)           // fp32 branches

// ---------------- prelude ----------------

__global__ void k_prep(const float* __restrict__ v, const float* __restrict__ labels,
                       const float* __restrict__ fxW1, const float* __restrict__ fyW1,
                       const float* __restrict__ hyW1) {
    __shared__ float bv[256];
    __shared__ int   bi[256];
    int t = threadIdx.x;
    for (int i = t; i < NN; i += 256) {
        #pragma unroll
        for (int j = 0; j < 7; j++) g_vc[i * 8 + j] = v[i * 7 + j];
        g_vc[i * 8 + 7] = labels[i];
    }
    float best = -1e30f; int idx = 0;
    for (int i = t; i < NN; i += 256) {
        float l = labels[i];
        if (l > best) { best = l; idx = i; }
    }
    bv[t] = best; bi[t] = idx;
    __syncthreads();
    for (int s = 128; s > 0; s >>= 1) {
        if (t < s) {
            if (bv[t + s] > bv[t] || (bv[t + s] == bv[t] && bi[t + s] < bi[t])) {
                bv[t] = bv[t + s]; bi[t] = bi[t + s];
            }
        }
        __syncthreads();
    }
    if (t < 8) g_goal[t] = g_vc[bi[0] * 8 + t];
    for (int i = t; i < 4096; i += 256) {
        g_A1[i] = fxW1[i] + fxW1[4096 + i];
        g_B1[i] = fxW1[8192 + i] - fxW1[i];
        g_A2[i] = fyW1[i] + fyW1[4096 + i];
        g_B2[i] = fyW1[8192 + i] - fyW1[i];
        if (i < 512) {
            g_Ay[i] = hyW1[i] + hyW1[512 + i];
            g_By[i] = hyW1[1024 + i] - hyW1[i];
        }
    }
}

__global__ void k_init(const float* __restrict__ W1, const float* __restrict__ b1,
                       const float* __restrict__ W2, const float* __restrict__ b2) {
    int i = blockIdx.x;
    int c = threadIdx.x;                 // 64 threads
    __shared__ float z[32], h[64];
    if (c < 8) {
        float vcv = g_vc[i * 8 + c];
        float gl  = g_goal[c];
        float d   = vcv - gl;
        z[c] = vcv; z[8 + c] = gl; z[16 + c] = d; z[24 + c] = d * d;
    }
    __syncthreads();
    float acc = b1[c];
    #pragma unroll
    for (int k = 0; k < 32; k++) acc += z[k] * W1[k * 64 + c];
    h[c] = fmaxf(acc, 0.0f);
    __syncthreads();
    float o = b2[c];
    #pragma unroll 16
    for (int k = 0; k < 64; k++) o += h[k] * W2[k * 64 + c];
    g_x[i * 64 + c] = o;
    float r = 0.f, s = 0.f;
    #pragma unroll
    for (int k = 0; k < 8; k++) {
        r += z[k] * g_Ay[k * 64 + c];
        s += z[k] * g_By[k * 64 + c];
    }
    g_Py[i * 64 + c] = r;
    g_Qy[i * 64 + c] = s;
}

// ---------------- fx edge kernel: tf32 MMA, pre-converted activations ----------------
__global__ void __launch_bounds__(512, 2)
k_fx_edge(const float* __restrict__ Wy, const float* __restrict__ b1,
          const float* __restrict__ W2, const float* __restrict__ b2,
          const int* __restrict__ src, const int* __restrict__ tgt) {
    extern __shared__ float sm[];
    float* Ws1 = sm;                 // Wy
    float* Ws2 = sm + 4096;          // W2
    float* act = sm + 8192;          // tf32 bits, [row][AST]; ys then hs
    int tid = threadIdx.x;
    int e0  = blockIdx.x * 64;
    for (int idx = tid; idx < 4096; idx += 512) {
        Ws1[idx] = Wy[idx];
        Ws2[idx] = W2[idx];
        int e = idx >> 6, k = idx & 63;
        act[e * AST + k] = __uint_as_float(tf32c(g_y[(e0 + e) * 64 + k]));
    }
    __syncthreads();

    int lane = tid & 31, wid = tid >> 5;
    int gr = lane >> 2, tig = lane & 3;
    int e0w = (wid >> 2) << 4;
    int n0  = (wid & 3) << 4;

    unsigned byA0[8], byA1[8], byB0[8], byB1[8];
    #pragma unroll
    for (int kc = 0; kc < 8; kc++) {
        int kb = kc * 8 + tig;
        byA0[kc] = tf32c(Ws1[kb * 64 + n0 + gr]);
        byA1[kc] = tf32c(Ws1[(kb + 4) * 64 + n0 + gr]);
        byB0[kc] = tf32c(Ws1[kb * 64 + n0 + 8 + gr]);
        byB1[kc] = tf32c(Ws1[(kb + 4) * 64 + n0 + 8 + gr]);
    }

    // ---- GEMM 1: y @ Wy (plain LDS, no cvt) ----
    float dA0 = 0.f, dA1 = 0.f, dA2 = 0.f, dA3 = 0.f;
    float dB0 = 0.f, dB1 = 0.f, dB2 = 0.f, dB3 = 0.f;
    #pragma unroll
    for (int kc = 0; kc < 8; kc++) {
        int ac = kc * 8 + tig;
        int ar = e0w + gr;
        unsigned a0 = __float_as_uint(act[ar * AST + ac]);
        unsigned a1 = __float_as_uint(act[(ar + 8) * AST + ac]);
        unsigned a2 = __float_as_uint(act[ar * AST + ac + 4]);
        unsigned a3 = __float_as_uint(act[(ar + 8) * AST + ac + 4]);
        MMA_TF32(dA0, dA1, dA2, dA3, a0, a1, a2, a3, byA0[kc], byA1[kc]);
        MMA_TF32(dB0, dB1, dB2, dB3, a0, a1, a2, a3, byB0[kc], byB1[kc]);
    }

    // ---- epilogue 1: h = relu(d + Pf[src] + Qf[tgt] + b1) in regs ----
    int r1 = e0w + gr, r2 = r1 + 8;
    int e1 = e0 + r1, e2 = e0 + r2;
    int c0 = n0 + tig * 2, c1 = n0 + 8 + tig * 2;
    float h00, h01, h10, h11, h20, h21, h30, h31;
    {
        int s1 = src[e1], t1 = tgt[e1], s2 = src[e2], t2 = tgt[e2];
        float2 p, q;
        p = *(const float2*)&g_Pf[s1 * 64 + c0]; q = *(const float2*)&g_Qf[t1 * 64 + c0];
        h00 = fmaxf(dA0 + p.x + q.x + b1[c0],     0.f);
        h01 = fmaxf(dA1 + p.y + q.y + b1[c0 + 1], 0.f);
        p = *(const float2*)&g_Pf[s2 * 64 + c0]; q = *(const float2*)&g_Qf[t2 * 64 + c0];
        h10 = fmaxf(dA2 + p.x + q.x + b1[c0],     0.f);
        h11 = fmaxf(dA3 + p.y + q.y + b1[c0 + 1], 0.f);
        p = *(const float2*)&g_Pf[s1 * 64 + c1]; q = *(const float2*)&g_Qf[t1 * 64 + c1];
        h20 = fmaxf(dB0 + p.x + q.x + b1[c1],     0.f);
        h21 = fmaxf(dB1 + p.y + q.y + b1[c1 + 1], 0.f);
        p = *(const float2*)&g_Pf[s2 * 64 + c1]; q = *(const float2*)&g_Qf[t2 * 64 + c1];
        h30 = fmaxf(dB2 + p.x + q.x + b1[c1],     0.f);
        h31 = fmaxf(dB3 + p.y + q.y + b1[c1 + 1], 0.f);
    }
    __syncthreads();   // all GEMM-1 reads of act done
    // store h as tf32 bits into act
    act[r1 * AST + c0]     = __uint_as_float(tf32c(h00));
    act[r1 * AST + c0 + 1] = __uint_as_float(tf32c(h01));
    act[r2 * AST + c0]     = __uint_as_float(tf32c(h10));
    act[r2 * AST + c0 + 1] = __uint_as_float(tf32c(h11));
    act[r1 * AST + c1]     = __uint_as_float(tf32c(h20));
    act[r1 * AST + c1 + 1] = __uint_as_float(tf32c(h21));
    act[r2 * AST + c1]     = __uint_as_float(tf32c(h30));
    act[r2 * AST + c1 + 1] = __uint_as_float(tf32c(h31));
    // preload W2 fragments (reuse regs)
    #pragma unroll
    for (int kc = 0; kc < 8; kc++) {
        int kb = kc * 8 + tig;
        byA0[kc] = tf32c(Ws2[kb * 64 + n0 + gr]);
        byA1[kc] = tf32c(Ws2[(kb + 4) * 64 + n0 + gr]);
        byB0[kc] = tf32c(Ws2[kb * 64 + n0 + 8 + gr]);
        byB1[kc] = tf32c(Ws2[(kb + 4) * 64 + n0 + 8 + gr]);
    }
    __syncthreads();

    // ---- GEMM 2: h @ W2 ----
    dA0 = dA1 = dA2 = dA3 = 0.f;
    dB0 = dB1 = dB2 = dB3 = 0.f;
    #pragma unroll
    for (int kc = 0; kc < 8; kc++) {
        int ac = kc * 8 + tig;
        int ar = e0w + gr;
        unsigned a0 = __float_as_uint(act[ar * AST + ac]);
        unsigned a1 = __float_as_uint(act[(ar + 8) * AST + ac]);
        unsigned a2 = __float_as_uint(act[ar * AST + ac + 4]);
        unsigned a3 = __float_as_uint(act[(ar + 8) * AST + ac + 4]);
        MMA_TF32(dA0, dA1, dA2, dA3, a0, a1, a2, a3, byA0[kc], byA1[kc]);
        MMA_TF32(dB0, dB1, dB2, dB3, a0, a1, a2, a3, byB0[kc], byB1[kc]);
    }

    // ---- epilogue 2: msg = d + b2 ----
    *(float2*)&g_msg[e1 * 64 + c0] = make_float2(dA0 + b2[c0], dA1 + b2[c0 + 1]);
    *(float2*)&g_msg[e2 * 64 + c0] = make_float2(dA2 + b2[c0], dA3 + b2[c0 + 1]);
    *(float2*)&g_msg[e1 * 64 + c1] = make_float2(dB0 + b2[c1], dB1 + b2[c1 + 1]);
    *(float2*)&g_msg[e2 * 64 + c1] = make_float2(dB2 + b2[c1], dB3 + b2[c1 + 1]);
}

// ---------------- fused edge-y + node_A: fp32 split-k (R12 version) ----------------
template <int MODE>
__global__ void __launch_bounds__(512, 3)
k_eyA(const float* __restrict__ b1, const float* __restrict__ W2,
      const float* __restrict__ b2,
      const int* __restrict__ src, const int* __restrict__ tgt) {
    extern __shared__ float sm[];
    int tid = threadIdx.x;

    if (blockIdx.x < EB2) {
        float* Ws = sm;
        float* hs = sm + 4096;
        int e0 = blockIdx.x * 64;
        for (int idx = tid; idx < 4096; idx += 512) Ws[idx] = W2[idx];
        {
            int nl = tid >> 3, cc = (tid & 7) << 3;
            int e = e0 + nl;
            int s = src[e], t = tgt[e];
            float4 p0 = *(const float4*)&g_Py[t * 64 + cc];
            float4 p1 = *(const float4*)&g_Py[t * 64 + cc + 4];
            float4 q0 = *(const float4*)&g_Qy[s * 64 + cc];
            float4 q1 = *(const float4*)&g_Qy[s * 64 + cc + 4];
            hs[(cc + 0) * 65 + nl] = fmaxf(p0.x + q0.x + b1[cc + 0], 0.f);
            hs[(cc + 1) * 65 + nl] = fmaxf(p0.y + q0.y + b1[cc + 1], 0.f);
            hs[(cc + 2) * 65 + nl] = fmaxf(p0.z + q0.z + b1[cc + 2], 0.f);
            hs[(cc + 3) * 65 + nl] = fmaxf(p0.w + q0.w + b1[cc + 3], 0.f);
            hs[(cc + 4) * 65 + nl] = fmaxf(p1.x + q1.x + b1[cc + 4], 0.f);
            hs[(cc + 5) * 65 + nl] = fmaxf(p1.y + q1.y + b1[cc + 5], 0.f);
            hs[(cc + 6) * 65 + nl] = fmaxf(p1.z + q1.z + b1[cc + 6], 0.f);
            hs[(cc + 7) * 65 + nl] = fmaxf(p1.w + q1.w + b1[cc + 7], 0.f);
        }
        __syncthreads();
        int lane = tid & 31;
        int o  = ((tid >> 5) << 4) | (lane & 15);
        int el = o >> 3, c0 = (o & 7) << 3;
        int kh = lane >> 4;
        int eA = e0 + el, eB = eA + 32;
        float accA[8], accB[8];
        #pragma unroll
        for (int j = 0; j < 8; j++) { accA[j] = 0.f; accB[j] = 0.f; }
        #pragma unroll 4
        for (int kk = 0; kk < 32; kk++) {
            int k = (kk << 1) | kh;
            float hA = hs[k * 65 + el];
            float hB = hs[k * 65 + el + 32];
            float4 w0 = *(const float4*)&Ws[k * 64 + c0];
            float4 w1 = *(const float4*)&Ws[k * 64 + c0 + 4];
            FMA8(accA, hA, w0, w1);
            FMA8(accB, hB, w0, w1);
        }
        #pragma unroll
        for (int j = 0; j < 8; j++) {
            accA[j] += __shfl_xor_sync(0xffffffffu, accA[j], 16);
            accB[j] += __shfl_xor_sync(0xffffffffu, accB[j], 16);
        }
        if (kh == 0) {
            #pragma unroll
            for (int j = 0; j < 8; j++) { accA[j] += b2[c0 + j]; accB[j] += b2[c0 + j]; }
            if (MODE == 0) {
                *(float4*)&g_y[eA * 64 + c0]     = make_float4(accA[0], accA[1], accA[2], accA[3]);
                *(float4*)&g_y[eA * 64 + c0 + 4] = make_float4(accA[4], accA[5], accA[6], accA[7]);
                *(float4*)&g_y[eB * 64 + c0]     = make_float4(accB[0], accB[1], accB[2], accB[3]);
                *(float4*)&g_y[eB * 64 + c0 + 4] = make_float4(accB[4], accB[5], accB[6], accB[7]);
            } else {
                float4 ya0 = *(const float4*)&g_y[eA * 64 + c0];
                float4 ya1 = *(const float4*)&g_y[eA * 64 + c0 + 4];
                float4 yb0 = *(const float4*)&g_y[eB * 64 + c0];
                float4 yb1 = *(const float4*)&g_y[eB * 64 + c0 + 4];
                *(float4*)&g_y[eA * 64 + c0] = make_float4(
                    fmaxf(ya0.x, accA[0]), fmaxf(ya0.y, accA[1]),
                    fmaxf(ya0.z, accA[2]), fmaxf(ya0.w, accA[3]));
                *(float4*)&g_y[eA * 64 + c0 + 4] = make_float4(
                    fmaxf(ya1.x, accA[4]), fmaxf(ya1.y, accA[5]),
                    fmaxf(ya1.z, accA[6]), fmaxf(ya1.w, accA[7]));
                *(float4*)&g_y[eB * 64 + c0] = make_float4(
                    fmaxf(yb0.x, accB[0]), fmaxf(yb0.y, accB[1]),
                    fmaxf(yb0.z, accB[2]), fmaxf(yb0.w, accB[3]));
                *(float4*)&g_y[eB * 64 + c0 + 4] = make_float4(
                    fmaxf(yb1.x, accB[4]), fmaxf(yb1.y, accB[5]),
                    fmaxf(yb1.z, accB[6]), fmaxf(yb1.w, accB[7]));
            }
        }
    } else {
        float* Wa = sm;
        float* Wb = sm + 4096;
        float* xs = sm + 8192;
        int i0 = (blockIdx.x - EB2) * 64;
        for (int idx = tid; idx < 4096; idx += 512) {
            Wa[idx] = g_A1[idx];
            Wb[idx] = g_B1[idx];
            int nl2 = idx >> 6, k = idx & 63, i = i0 + nl2;
            xs[k * 65 + nl2] = (i < NN) ? g_x[i * 64 + k] : 0.f;
        }
        __syncthreads();
        int g  = tid >> 8;
        int t2 = tid & 255;
        int el = t2 >> 3, c0 = (t2 & 7) << 3;
        const float* W = g ? Wb : Wa;
        float aA[8], aB[8];
        #pragma unroll
        for (int j = 0; j < 8; j++) { aA[j] = 0.f; aB[j] = 0.f; }
        #pragma unroll 4
        for (int k = 0; k < 64; k++) {
            float xA = xs[k * 65 + el];
            float xB = xs[k * 65 + el + 32];
            float4 w0 = *(const float4*)&W[k * 64 + c0];
            float4 w1 = *(const float4*)&W[k * 64 + c0 + 4];
            FMA8(aA, xA, w0, w1);
            FMA8(aB, xB, w0, w1);
        }
        float* O = g ? g_Qf : g_Pf;
        int iA = i0 + el, iB = iA + 32;
        if (iA < NN) {
            *(float4*)&O[iA * 64 + c0]     = make_float4(aA[0], aA[1], aA[2], aA[3]);
            *(float4*)&O[iA * 64 + c0 + 4] = make_float4(aA[4], aA[5], aA[6], aA[7]);
        }
        if (iB < NN) {
            *(float4*)&O[iB * 64 + c0]     = make_float4(aB[0], aB[1], aB[2], aB[3]);
            *(float4*)&O[iB * 64 + c0 + 4] = make_float4(aB[4], aB[5], aB[6], aB[7]);
        }
    }
}

// ---------------- node_B: CSR gather-max + x update + split A2/B2 GEMMs ----------------
__global__ void __launch_bounds__(512, 3)
k_node_B() {
    extern __shared__ float sm[];
    float* Wa = sm;
    float* Wb = sm + 4096;
    float* xs = sm + 8192;
    int tid = threadIdx.x;
    int i0  = blockIdx.x * 64;
    for (int idx = tid; idx < 4096; idx += 512) {
        Wa[idx] = g_A2[idx];
        Wb[idx] = g_B2[idx];
    }
    {
        int nl = tid >> 3, cc = (tid & 7) << 3;
        int i = i0 + nl;
        if (i < NN) {
            float m[8];
            #pragma unroll
            for (int j = 0; j < 8; j++) m[j] = NEG_INF;
            int p0 = g_rowptr[i], p1 = g_rowptr[i + 1];
            for (int p = p0; p < p1; p++) {
                int e = g_cols[p];
                float4 a = *(const float4*)&g_msg[e * 64 + cc];
                float4 b = *(const float4*)&g_msg[e * 64 + cc + 4];
                m[0] = fmaxf(m[0], a.x); m[1] = fmaxf(m[1], a.y);
                m[2] = fmaxf(m[2], a.z); m[3] = fmaxf(m[3], a.w);
                m[4] = fmaxf(m[4], b.x); m[5] = fmaxf(m[5], b.y);
                m[6] = fmaxf(m[6], b.z); m[7] = fmaxf(m[7], b.w);
            }
            if (p1 == p0) {
                #pragma unroll
                for (int j = 0; j < 8; j++) m[j] = 0.f;
            }
            #pragma unroll
            for (int j = 0; j < 8; j++) {
                float xn = fmaxf(g_x[i * 64 + cc + j], m[j]);
                g_x[i * 64 + cc + j] = xn;
                xs[(cc + j) * 65 + nl] = xn;
            }
        } else {
            #pragma unroll
            for (int j = 0; j < 8; j++) xs[(cc + j) * 65 + nl] = 0.f;
        }
    }
    __syncthreads();
    int g  = tid >> 8;
    int t2 = tid & 255;
    int el = t2 >> 3, c0 = (t2 & 7) << 3;
    const float* W = g ? Wb : Wa;
    float aA[8], aB[8];
    #pragma unroll
    for (int j = 0; j < 8; j++) { aA[j] = 0.f; aB[j] = 0.f; }
    #pragma unroll 4
    for (int k = 0; k < 64; k++) {
        float xA = xs[k * 65 + el];
        float xB = xs[k * 65 + el + 32];
        float4 w0 = *(const float4*)&W[k * 64 + c0];
        float4 w1 = *(const float4*)&W[k * 64 + c0 + 4];
        FMA8(aA, xA, w0, w1);
        FMA8(aB, xB, w0, w1);
    }
    float* O = g ? g_Qy : g_Py;
    int iA = i0 + el, iB = iA + 32;
    if (iA < NN) {
        *(float4*)&O[iA * 64 + c0]     = make_float4(aA[0], aA[1], aA[2], aA[3]);
        *(float4*)&O[iA * 64 + c0 + 4] = make_float4(aA[4], aA[5], aA[6], aA[7]);
    }
    if (iB < NN) {
        *(float4*)&O[iB * 64 + c0]     = make_float4(aB[0], aB[1], aB[2], aB[3]);
        *(float4*)&O[iB * 64 + c0 + 4] = make_float4(aB[4], aB[5], aB[6], aB[7]);
    }
}

// ---------------- CSR build ----------------
__global__ void k_csr(const int* __restrict__ tgt) {
    __shared__ int cnt[1536];
    __shared__ int buf[1536];
    __shared__ int cur[1536];
    int tid = threadIdx.x;                 // 1024 threads
    for (int i = tid; i < 1536; i += 1024) cnt[i] = 0;
    __syncthreads();
    for (int e = tid; e < NEDGE; e += 1024) atomicAdd(&cnt[tgt[e]], 1);
    __syncthreads();
    int* s_ = cnt; int* d_ = buf;
    for (int off = 1; off < 1536; off <<= 1) {
        for (int i = tid; i < 1536; i += 1024)
            d_[i] = s_[i] + ((i >= off) ? s_[i - off] : 0);
        __syncthreads();
        int* tmp = s_; s_ = d_; d_ = tmp;
    }
    if (tid == 0) g_rowptr[0] = 0;
    for (int i = tid; i < NN; i += 1024) g_rowptr[i + 1] = s_[i];
    for (int i = tid; i < 1536; i += 1024) cur[i] = (i == 0) ? 0 : s_[i - 1];
    __syncthreads();
    for (int e = tid; e < NEDGE; e += 1024) {
        int p = atomicAdd(&cur[tgt[e]], 1);
        g_cols[p] = e;
    }
}

// ---------------- output machinery ----------------
__global__ void k_winner_init() {
    int i = blockIdx.x * blockDim.x + threadIdx.x;
    if (i < NN * NN) g_winner[i] = -1;
}

__global__ void k_winner(const int* __restrict__ src, const int* __restrict__ tgt) {
    int e = blockIdx.x * blockDim.x + threadIdx.x;
    if (e < NEDGE) atomicMax(&g_winner[src[e] * NN + tgt[e]], e);
}

__global__ void k_zero(float4* __restrict__ out4) {
    const int total = NN * NN * (EDIM / 4);
    const float4 z = make_float4(0.f, 0.f, 0.f, 0.f);
    for (int idx = blockIdx.x * blockDim.x + threadIdx.x; idx < total;
         idx += gridDim.x * blockDim.x) {
        int row = idx >> 4;
        if (g_winner[row] < 0) out4[idx] = z;
    }
}

__global__ void k_scatter(const int* __restrict__ src, const int* __restrict__ tgt,
                          float* __restrict__ out) {
    int idx = blockIdx.x * blockDim.x + threadIdx.x;
    if (idx < NEDGE * EDIM) {
        int e = idx >> 6, c = idx & 63;
        int s = src[e], t = tgt[e];
        long long slot = (long long)s * NN + t;
        if (g_winner[slot] == e) out[slot * 64 + c] = g_y[idx];
    }
}

__global__ void k_out_x(float* __restrict__ out) {
    int i = blockIdx.x * blockDim.x + threadIdx.x;
    if (i < NN * EDIM) out[(long long)NN * NN * EDIM + i] = g_x[i];
}

// ---------------- launch ----------------
extern "C" void kernel_launch(void* const* d_in, const int* in_sizes, int n_in,
                              void* d_out, int out_size) {
    const float* v      = (const float*)d_in[0];
    const float* labels = (const float*)d_in[1];
    const int*   ei     = (const int*)d_in[4];
    const float* hx_W1 = (const float*)d_in[6],  *hx_b1 = (const float*)d_in[7];
    const float* hx_W2 = (const float*)d_in[8],  *hx_b2 = (const float*)d_in[9];
    const float* hy_W1 = (const float*)d_in[10], *hy_b1 = (const float*)d_in[11];
    const float* hy_W2 = (const float*)d_in[12], *hy_b2 = (const float*)d_in[13];
    const float* fx_W1 = (const float*)d_in[14], *fx_b1 = (const float*)d_in[15];
    const float* fx_W2 = (const float*)d_in[16], *fx_b2 = (const float*)d_in[17];
    const float* fy_W1 = (const float*)d_in[18], *fy_b1 = (const float*)d_in[19];
    const float* fy_W2 = (const float*)d_in[20], *fy_b2 = (const float*)d_in[21];

    const int* src = ei;
    const int* tgt = ei + NEDGE;
    float* out = (float*)d_out;

    static bool attr_done = false;
    if (!attr_done) {
        cudaFuncSetAttribute(k_fx_edge, cudaFuncAttributeMaxDynamicSharedMemorySize,
                             FX_SM * sizeof(float));
        cudaFuncSetAttribute(k_eyA<0>, cudaFuncAttributeMaxDynamicSharedMemorySize,
                             EYA_SM * sizeof(float));
        cudaFuncSetAttribute(k_eyA<1>, cudaFuncAttributeMaxDynamicSharedMemorySize,
                             EYA_SM * sizeof(float));
        cudaFuncSetAttribute(k_node_B, cudaFuncAttributeMaxDynamicSharedMemorySize,
                             EYA_SM * sizeof(float));
        attr_done = true;
    }

    cudaStream_t s2;
    cudaStreamCreateWithFlags(&s2, cudaStreamNonBlocking);
    cudaEvent_t evFork, evCSR, evJoin;
    cudaEventCreateWithFlags(&evFork, cudaEventDisableTiming);
    cudaEventCreateWithFlags(&evCSR, cudaEventDisableTiming);
    cudaEventCreateWithFlags(&evJoin, cudaEventDisableTiming);

    cudaEventRecord(evFork, 0);

    // main pipeline head — k_fx_edge at submission index 3 for ncu
    k_prep<<<1, 256>>>(v, labels, fx_W1, fy_W1, hy_W1);                        // #0
    k_init<<<NN, 64>>>(hx_W1, hx_b1, hx_W2, hx_b2);                            // #1
    k_eyA<0><<<EB2 + NT2, 512, EYA_SM * sizeof(float)>>>(hy_b1, hy_W2, hy_b2, src, tgt); // #2
    k_fx_edge<<<EB2, 512, FX_SM * sizeof(float)>>>(fx_W1 + 192 * 64, fx_b1, fx_W2, fx_b2, src, tgt); // #3

    // side stream: CSR + winner + zero
    cudaStreamWaitEvent(s2, evFork, 0);
    k_csr<<<1, 1024, 0, s2>>>(tgt);
    cudaEventRecord(evCSR, s2);
    k_winner_init<<<(NN * NN + 255) / 256, 256, 0, s2>>>();
    k_winner<<<(NEDGE + 255) / 256, 256, 0, s2>>>(src, tgt);
    k_zero<<<1184, 512, 0, s2>>>((float4*)out);
    cudaEventRecord(evJoin, s2);

    // loop: fx_edge -> node_B -> ey+nodeA
    cudaStreamWaitEvent(0, evCSR, 0);
    for (int it = 0; it < LOOPN; it++) {
        if (it > 0)
            k_fx_edge<<<EB2, 512, FX_SM * sizeof(float)>>>(fx_W1 + 192 * 64, fx_b1, fx_W2, fx_b2, src, tgt);
        k_node_B<<<NT2, 512, EYA_SM * sizeof(float)>>>();
        k_eyA<1><<<EB2 + NT2, 512, EYA_SM * sizeof(float)>>>(fy_b1, fy_W2, fy_b2, src, tgt);
    }

    // join side, then outputs
    cudaStreamWaitEvent(0, evJoin, 0);
    k_scatter<<<(NEDGE * EDIM + 255) / 256, 256>>>(src, tgt, out);
    k_out_x<<<(NN * EDIM + 255) / 256, 256>>>(out);
}

// round 15
// speedup vs baseline: 1.6378x; 1.6378x over previous
#include <cuda_runtime.h>
#include <cuda_bf16.h>

#define NN    1500
#define NEDGE 24000
#define EDIM  64
#define LOOPN 10
#define EB2   375            // NEDGE/64 edge tiles
#define NT2   24             // ceil(NN/64) node tiles

// ---------------- device scratch ----------------
__device__ float g_vc[NN * 8];
__device__ float g_goal[8];
__device__ float g_x[NN * EDIM];
__device__ float g_y[NEDGE * EDIM];
__device__ float g_msg[NEDGE * EDIM];
__device__ float g_Pf[NN * EDIM], g_Qf[NN * EDIM];
__device__ float g_Py[NN * EDIM], g_Qy[NN * EDIM];
__device__ float g_A1[EDIM * EDIM], g_B1[EDIM * EDIM];
__device__ float g_A2[EDIM * EDIM], g_B2[EDIM * EDIM];
__device__ float g_Ay[8 * EDIM],   g_By[8 * EDIM];
__device__ int   g_rowptr[NN + 1];
__device__ int   g_cols[NEDGE];
__device__ int   g_winner[NN * NN];

#define NEG_INF __int_as_float(0xff800000)

#define FMA8(acc, v, w0, w1)                                   \
    {   acc[0] += (v) * (w0).x; acc[1] += (v) * (w0).y;        \
        acc[2] += (v) * (w0).z; acc[3] += (v) * (w0).w;        \
        acc[4] += (v) * (w1).x; acc[5] += (v) * (w1).y;        \
        acc[6] += (v) * (w1).z; acc[7] += (v) * (w1).w; }

// tf32 convert (round-to-nearest)
__device__ __forceinline__ unsigned tf32c(float x) {
    unsigned u;
    asm("cvt.rna.tf32.f32 %0, %1;" : "=r"(u) : "f"(x));
    return u;
}

#define MMA_TF32(d0, d1, d2, d3, a0, a1, a2, a3, b0, b1)                    \
    asm volatile("mma.sync.aligned.m16n8k8.row.col.f32.tf32.tf32.f32 "      \
                 "{%0,%1,%2,%3}, {%4,%5,%6,%7}, {%8,%9}, {%0,%1,%2,%3};"    \
                 : "+f"(d0), "+f"(d1), "+f"(d2), "+f"(d3)                   \
                 : "r"(a0), "r"(a1), "r"(a2), "r"(a3), "r"(b0), "r"(b1))

// smem (floats)
#define AST 68
#define FX_SM  (4096 + 4096 + 64 * AST)       // Wy, W2, act (reused ys->hs) = 50 KB
#define EYA_SM (4096 + 4096 + 4160)           // fp32 branches

// ---------------- prelude ----------------

__global__ void k_prep(const float* __restrict__ v, const float* __restrict__ labels,
                       const float* __restrict__ fxW1, const float* __restrict__ fyW1,
                       const float* __restrict__ hyW1) {
    __shared__ float bv[256];
    __shared__ int   bi[256];
    int t = threadIdx.x;
    for (int i = t; i < NN; i += 256) {
        #pragma unroll
        for (int j = 0; j < 7; j++) g_vc[i * 8 + j] = v[i * 7 + j];
        g_vc[i * 8 + 7] = labels[i];
    }
    float best = -1e30f; int idx = 0;
    for (int i = t; i < NN; i += 256) {
        float l = labels[i];
        if (l > best) { best = l; idx = i; }
    }
    bv[t] = best; bi[t] = idx;
    __syncthreads();
    for (int s = 128; s > 0; s >>= 1) {
        if (t < s) {
            if (bv[t + s] > bv[t] || (bv[t + s] == bv[t] && bi[t + s] < bi[t])) {
                bv[t] = bv[t + s]; bi[t] = bi[t + s];
            }
        }
        __syncthreads();
    }
    if (t < 8) g_goal[t] = g_vc[bi[0] * 8 + t];
    for (int i = t; i < 4096; i += 256) {
        g_A1[i] = fxW1[i] + fxW1[4096 + i];
        g_B1[i] = fxW1[8192 + i] - fxW1[i];
        g_A2[i] = fyW1[i] + fyW1[4096 + i];
        g_B2[i] = fyW1[8192 + i] - fyW1[i];
        if (i < 512) {
            g_Ay[i] = hyW1[i] + hyW1[512 + i];
            g_By[i] = hyW1[1024 + i] - hyW1[i];
        }
    }
}

__global__ void k_init(const float* __restrict__ W1, const float* __restrict__ b1,
                       const float* __restrict__ W2, const float* __restrict__ b2) {
    int i = blockIdx.x;
    int c = threadIdx.x;                 // 64 threads
    __shared__ float z[32], h[64];
    if (c < 8) {
        float vcv = g_vc[i * 8 + c];
        float gl  = g_goal[c];
        float d   = vcv - gl;
        z[c] = vcv; z[8 + c] = gl; z[16 + c] = d; z[24 + c] = d * d;
    }
    __syncthreads();
    float acc = b1[c];
    #pragma unroll
    for (int k = 0; k < 32; k++) acc += z[k] * W1[k * 64 + c];
    h[c] = fmaxf(acc, 0.0f);
    __syncthreads();
    float o = b2[c];
    #pragma unroll 16
    for (int k = 0; k < 64; k++) o += h[k] * W2[k * 64 + c];
    g_x[i * 64 + c] = o;
    float r = 0.f, s = 0.f;
    #pragma unroll
    for (int k = 0; k < 8; k++) {
        r += z[k] * g_Ay[k * 64 + c];
        s += z[k] * g_By[k * 64 + c];
    }
    g_Py[i * 64 + c] = r;
    g_Qy[i * 64 + c] = s;
}

// ---------------- fx edge kernel: tf32 MMA, pre-converted activations ----------------
__global__ void __launch_bounds__(512, 2)
k_fx_edge(const float* __restrict__ Wy, const float* __restrict__ b1,
          const float* __restrict__ W2, const float* __restrict__ b2,
          const int* __restrict__ src, const int* __restrict__ tgt) {
    extern __shared__ float sm[];
    float* Ws1 = sm;                 // Wy
    float* Ws2 = sm + 4096;          // W2
    float* act = sm + 8192;          // tf32 bits, [row][AST]; ys then hs
    int tid = threadIdx.x;
    int e0  = blockIdx.x * 64;
    for (int idx = tid; idx < 4096; idx += 512) {
        Ws1[idx] = Wy[idx];
        Ws2[idx] = W2[idx];
        int e = idx >> 6, k = idx & 63;
        act[e * AST + k] = __uint_as_float(tf32c(g_y[(e0 + e) * 64 + k]));
    }
    __syncthreads();

    int lane = tid & 31, wid = tid >> 5;
    int gr = lane >> 2, tig = lane & 3;
    int e0w = (wid >> 2) << 4;
    int n0  = (wid & 3) << 4;

    unsigned byA0[8], byA1[8], byB0[8], byB1[8];
    #pragma unroll
    for (int kc = 0; kc < 8; kc++) {
        int kb = kc * 8 + tig;
        byA0[kc] = tf32c(Ws1[kb * 64 + n0 + gr]);
        byA1[kc] = tf32c(Ws1[(kb + 4) * 64 + n0 + gr]);
        byB0[kc] = tf32c(Ws1[kb * 64 + n0 + 8 + gr]);
        byB1[kc] = tf32c(Ws1[(kb + 4) * 64 + n0 + 8 + gr]);
    }

    // ---- GEMM 1: y @ Wy ----
    float dA0 = 0.f, dA1 = 0.f, dA2 = 0.f, dA3 = 0.f;
    float dB0 = 0.f, dB1 = 0.f, dB2 = 0.f, dB3 = 0.f;
    #pragma unroll
    for (int kc = 0; kc < 8; kc++) {
        int ac = kc * 8 + tig;
        int ar = e0w + gr;
        unsigned a0 = __float_as_uint(act[ar * AST + ac]);
        unsigned a1 = __float_as_uint(act[(ar + 8) * AST + ac]);
        unsigned a2 = __float_as_uint(act[ar * AST + ac + 4]);
        unsigned a3 = __float_as_uint(act[(ar + 8) * AST + ac + 4]);
        MMA_TF32(dA0, dA1, dA2, dA3, a0, a1, a2, a3, byA0[kc], byA1[kc]);
        MMA_TF32(dB0, dB1, dB2, dB3, a0, a1, a2, a3, byB0[kc], byB1[kc]);
    }

    // ---- epilogue 1 ----
    int r1 = e0w + gr, r2 = r1 + 8;
    int e1 = e0 + r1, e2 = e0 + r2;
    int c0 = n0 + tig * 2, c1 = n0 + 8 + tig * 2;
    float h00, h01, h10, h11, h20, h21, h30, h31;
    {
        int s1 = src[e1], t1 = tgt[e1], s2 = src[e2], t2 = tgt[e2];
        float2 p, q;
        p = *(const float2*)&g_Pf[s1 * 64 + c0]; q = *(const float2*)&g_Qf[t1 * 64 + c0];
        h00 = fmaxf(dA0 + p.x + q.x + b1[c0],     0.f);
        h01 = fmaxf(dA1 + p.y + q.y + b1[c0 + 1], 0.f);
        p = *(const float2*)&g_Pf[s2 * 64 + c0]; q = *(const float2*)&g_Qf[t2 * 64 + c0];
        h10 = fmaxf(dA2 + p.x + q.x + b1[c0],     0.f);
        h11 = fmaxf(dA3 + p.y + q.y + b1[c0 + 1], 0.f);
        p = *(const float2*)&g_Pf[s1 * 64 + c1]; q = *(const float2*)&g_Qf[t1 * 64 + c1];
        h20 = fmaxf(dB0 + p.x + q.x + b1[c1],     0.f);
        h21 = fmaxf(dB1 + p.y + q.y + b1[c1 + 1], 0.f);
        p = *(const float2*)&g_Pf[s2 * 64 + c1]; q = *(const float2*)&g_Qf[t2 * 64 + c1];
        h30 = fmaxf(dB2 + p.x + q.x + b1[c1],     0.f);
        h31 = fmaxf(dB3 + p.y + q.y + b1[c1 + 1], 0.f);
    }
    __syncthreads();
    act[r1 * AST + c0]     = __uint_as_float(tf32c(h00));
    act[r1 * AST + c0 + 1] = __uint_as_float(tf32c(h01));
    act[r2 * AST + c0]     = __uint_as_float(tf32c(h10));
    act[r2 * AST + c0 + 1] = __uint_as_float(tf32c(h11));
    act[r1 * AST + c1]     = __uint_as_float(tf32c(h20));
    act[r1 * AST + c1 + 1] = __uint_as_float(tf32c(h21));
    act[r2 * AST + c1]     = __uint_as_float(tf32c(h30));
    act[r2 * AST + c1 + 1] = __uint_as_float(tf32c(h31));
    #pragma unroll
    for (int kc = 0; kc < 8; kc++) {
        int kb = kc * 8 + tig;
        byA0[kc] = tf32c(Ws2[kb * 64 + n0 + gr]);
        byA1[kc] = tf32c(Ws2[(kb + 4) * 64 + n0 + gr]);
        byB0[kc] = tf32c(Ws2[kb * 64 + n0 + 8 + gr]);
        byB1[kc] = tf32c(Ws2[(kb + 4) * 64 + n0 + 8 + gr]);
    }
    __syncthreads();

    // ---- GEMM 2: h @ W2 ----
    dA0 = dA1 = dA2 = dA3 = 0.f;
    dB0 = dB1 = dB2 = dB3 = 0.f;
    #pragma unroll
    for (int kc = 0; kc < 8; kc++) {
        int ac = kc * 8 + tig;
        int ar = e0w + gr;
        unsigned a0 = __float_as_uint(act[ar * AST + ac]);
        unsigned a1 = __float_as_uint(act[(ar + 8) * AST + ac]);
        unsigned a2 = __float_as_uint(act[ar * AST + ac + 4]);
        unsigned a3 = __float_as_uint(act[(ar + 8) * AST + ac + 4]);
        MMA_TF32(dA0, dA1, dA2, dA3, a0, a1, a2, a3, byA0[kc], byA1[kc]);
        MMA_TF32(dB0, dB1, dB2, dB3, a0, a1, a2, a3, byB0[kc], byB1[kc]);
    }

    *(float2*)&g_msg[e1 * 64 + c0] = make_float2(dA0 + b2[c0], dA1 + b2[c0 + 1]);
    *(float2*)&g_msg[e2 * 64 + c0] = make_float2(dA2 + b2[c0], dA3 + b2[c0 + 1]);
    *(float2*)&g_msg[e1 * 64 + c1] = make_float2(dB0 + b2[c1], dB1 + b2[c1 + 1]);
    *(float2*)&g_msg[e2 * 64 + c1] = make_float2(dB2 + b2[c1], dB3 + b2[c1 + 1]);
}

// ---------------- fused edge-y + node_A: fp32 split-k ----------------
template <int MODE>
__global__ void __launch_bounds__(512, 3)
k_eyA(const float* __restrict__ b1, const float* __restrict__ W2,
      const float* __restrict__ b2,
      const int* __restrict__ src, const int* __restrict__ tgt) {
    extern __shared__ float sm[];
    int tid = threadIdx.x;

    if (blockIdx.x < EB2) {
        float* Ws = sm;
        float* hs = sm + 4096;
        int e0 = blockIdx.x * 64;
        for (int idx = tid; idx < 4096; idx += 512) Ws[idx] = W2[idx];
        {
            int nl = tid >> 3, cc = (tid & 7) << 3;
            int e = e0 + nl;
            int s = src[e], t = tgt[e];
            float4 p0 = *(const float4*)&g_Py[t * 64 + cc];
            float4 p1 = *(const float4*)&g_Py[t * 64 + cc + 4];
            float4 q0 = *(const float4*)&g_Qy[s * 64 + cc];
            float4 q1 = *(const float4*)&g_Qy[s * 64 + cc + 4];
            hs[(cc + 0) * 65 + nl] = fmaxf(p0.x + q0.x + b1[cc + 0], 0.f);
            hs[(cc + 1) * 65 + nl] = fmaxf(p0.y + q0.y + b1[cc + 1], 0.f);
            hs[(cc + 2) * 65 + nl] = fmaxf(p0.z + q0.z + b1[cc + 2], 0.f);
            hs[(cc + 3) * 65 + nl] = fmaxf(p0.w + q0.w + b1[cc + 3], 0.f);
            hs[(cc + 4) * 65 + nl] = fmaxf(p1.x + q1.x + b1[cc + 4], 0.f);
            hs[(cc + 5) * 65 + nl] = fmaxf(p1.y + q1.y + b1[cc + 5], 0.f);
            hs[(cc + 6) * 65 + nl] = fmaxf(p1.z + q1.z + b1[cc + 6], 0.f);
            hs[(cc + 7) * 65 + nl] = fmaxf(p1.w + q1.w + b1[cc + 7], 0.f);
        }
        __syncthreads();
        int lane = tid & 31;
        int o  = ((tid >> 5) << 4) | (lane & 15);
        int el = o >> 3, c0 = (o & 7) << 3;
        int kh = lane >> 4;
        int eA = e0 + el, eB = eA + 32;
        float accA[8], accB[8];
        #pragma unroll
        for (int j = 0; j < 8; j++) { accA[j] = 0.f; accB[j] = 0.f; }
        #pragma unroll 4
        for (int kk = 0; kk < 32; kk++) {
            int k = (kk << 1) | kh;
            float hA = hs[k * 65 + el];
            float hB = hs[k * 65 + el + 32];
            float4 w0 = *(const float4*)&Ws[k * 64 + c0];
            float4 w1 = *(const float4*)&Ws[k * 64 + c0 + 4];
            FMA8(accA, hA, w0, w1);
            FMA8(accB, hB, w0, w1);
        }
        #pragma unroll
        for (int j = 0; j < 8; j++) {
            accA[j] += __shfl_xor_sync(0xffffffffu, accA[j], 16);
            accB[j] += __shfl_xor_sync(0xffffffffu, accB[j], 16);
        }
        if (kh == 0) {
            #pragma unroll
            for (int j = 0; j < 8; j++) { accA[j] += b2[c0 + j]; accB[j] += b2[c0 + j]; }
            if (MODE == 0) {
                *(float4*)&g_y[eA * 64 + c0]     = make_float4(accA[0], accA[1], accA[2], accA[3]);
                *(float4*)&g_y[eA * 64 + c0 + 4] = make_float4(accA[4], accA[5], accA[6], accA[7]);
                *(float4*)&g_y[eB * 64 + c0]     = make_float4(accB[0], accB[1], accB[2], accB[3]);
                *(float4*)&g_y[eB * 64 + c0 + 4] = make_float4(accB[4], accB[5], accB[6], accB[7]);
            } else {
                float4 ya0 = *(const float4*)&g_y[eA * 64 + c0];
                float4 ya1 = *(const float4*)&g_y[eA * 64 + c0 + 4];
                float4 yb0 = *(const float4*)&g_y[eB * 64 + c0];
                float4 yb1 = *(const float4*)&g_y[eB * 64 + c0 + 4];
                *(float4*)&g_y[eA * 64 + c0] = make_float4(
                    fmaxf(ya0.x, accA[0]), fmaxf(ya0.y, accA[1]),
                    fmaxf(ya0.z, accA[2]), fmaxf(ya0.w, accA[3]));
                *(float4*)&g_y[eA * 64 + c0 + 4] = make_float4(
                    fmaxf(ya1.x, accA[4]), fmaxf(ya1.y, accA[5]),
                    fmaxf(ya1.z, accA[6]), fmaxf(ya1.w, accA[7]));
                *(float4*)&g_y[eB * 64 + c0] = make_float4(
                    fmaxf(yb0.x, accB[0]), fmaxf(yb0.y, accB[1]),
                    fmaxf(yb0.z, accB[2]), fmaxf(yb0.w, accB[3]));
                *(float4*)&g_y[eB * 64 + c0 + 4] = make_float4(
                    fmaxf(yb1.x, accB[4]), fmaxf(yb1.y, accB[5]),
                    fmaxf(yb1.z, accB[6]), fmaxf(yb1.w, accB[7]));
            }
        }
    } else {
        float* Wa = sm;
        float* Wb = sm + 4096;
        float* xs = sm + 8192;
        int i0 = (blockIdx.x - EB2) * 64;
        for (int idx = tid; idx < 4096; idx += 512) {
            Wa[idx] = g_A1[idx];
            Wb[idx] = g_B1[idx];
            int nl2 = idx >> 6, k = idx & 63, i = i0 + nl2;
            xs[k * 65 + nl2] = (i < NN) ? g_x[i * 64 + k] : 0.f;
        }
        __syncthreads();
        int g  = tid >> 8;
        int t2 = tid & 255;
        int el = t2 >> 3, c0 = (t2 & 7) << 3;
        const float* W = g ? Wb : Wa;
        float aA[8], aB[8];
        #pragma unroll
        for (int j = 0; j < 8; j++) { aA[j] = 0.f; aB[j] = 0.f; }
        #pragma unroll 4
        for (int k = 0; k < 64; k++) {
            float xA = xs[k * 65 + el];
            float xB = xs[k * 65 + el + 32];
            float4 w0 = *(const float4*)&W[k * 64 + c0];
            float4 w1 = *(const float4*)&W[k * 64 + c0 + 4];
            FMA8(aA, xA, w0, w1);
            FMA8(aB, xB, w0, w1);
        }
        float* O = g ? g_Qf : g_Pf;
        int iA = i0 + el, iB = iA + 32;
        if (iA < NN) {
            *(float4*)&O[iA * 64 + c0]     = make_float4(aA[0], aA[1], aA[2], aA[3]);
            *(float4*)&O[iA * 64 + c0 + 4] = make_float4(aA[4], aA[5], aA[6], aA[7]);
        }
        if (iB < NN) {
            *(float4*)&O[iB * 64 + c0]     = make_float4(aB[0], aB[1], aB[2], aB[3]);
            *(float4*)&O[iB * 64 + c0 + 4] = make_float4(aB[4], aB[5], aB[6], aB[7]);
        }
    }
}

// ---------------- node_B ----------------
__global__ void __launch_bounds__(512, 3)
k_node_B() {
    extern __shared__ float sm[];
    float* Wa = sm;
    float* Wb = sm + 4096;
    float* xs = sm + 8192;
    int tid = threadIdx.x;
    int i0  = blockIdx.x * 64;
    for (int idx = tid; idx < 4096; idx += 512) {
        Wa[idx] = g_A2[idx];
        Wb[idx] = g_B2[idx];
    }
    {
        int nl = tid >> 3, cc = (tid & 7) << 3;
        int i = i0 + nl;
        if (i < NN) {
            float m[8];
            #pragma unroll
            for (int j = 0; j < 8; j++) m[j] = NEG_INF;
            int p0 = g_rowptr[i], p1 = g_rowptr[i + 1];
            for (int p = p0; p < p1; p++) {
                int e = g_cols[p];
                float4 a = *(const float4*)&g_msg[e * 64 + cc];
                float4 b = *(const float4*)&g_msg[e * 64 + cc + 4];
                m[0] = fmaxf(m[0], a.x); m[1] = fmaxf(m[1], a.y);
                m[2] = fmaxf(m[2], a.z); m[3] = fmaxf(m[3], a.w);
                m[4] = fmaxf(m[4], b.x); m[5] = fmaxf(m[5], b.y);
                m[6] = fmaxf(m[6], b.z); m[7] = fmaxf(m[7], b.w);
            }
            if (p1 == p0) {
                #pragma unroll
                for (int j = 0; j < 8; j++) m[j] = 0.f;
            }
            #pragma unroll
            for (int j = 0; j < 8; j++) {
                float xn = fmaxf(g_x[i * 64 + cc + j], m[j]);
                g_x[i * 64 + cc + j] = xn;
                xs[(cc + j) * 65 + nl] = xn;
            }
        } else {
            #pragma unroll
            for (int j = 0; j < 8; j++) xs[(cc + j) * 65 + nl] = 0.f;
        }
    }
    __syncthreads();
    int g  = tid >> 8;
    int t2 = tid & 255;
    int el = t2 >> 3, c0 = (t2 & 7) << 3;
    const float* W = g ? Wb : Wa;
    float aA[8], aB[8];
    #pragma unroll
    for (int j = 0; j < 8; j++) { aA[j] = 0.f; aB[j] = 0.f; }
    #pragma unroll 4
    for (int k = 0; k < 64; k++) {
        float xA = xs[k * 65 + el];
        float xB = xs[k * 65 + el + 32];
        float4 w0 = *(const float4*)&W[k * 64 + c0];
        float4 w1 = *(const float4*)&W[k * 64 + c0 + 4];
        FMA8(aA, xA, w0, w1);
        FMA8(aB, xB, w0, w1);
    }
    float* O = g ? g_Qy : g_Py;
    int iA = i0 + el, iB = iA + 32;
    if (iA < NN) {
        *(float4*)&O[iA * 64 + c0]     = make_float4(aA[0], aA[1], aA[2], aA[3]);
        *(float4*)&O[iA * 64 + c0 + 4] = make_float4(aA[4], aA[5], aA[6], aA[7]);
    }
    if (iB < NN) {
        *(float4*)&O[iB * 64 + c0]     = make_float4(aB[0], aB[1], aB[2], aB[3]);
        *(float4*)&O[iB * 64 + c0 + 4] = make_float4(aB[4], aB[5], aB[6], aB[7]);
    }
}

// ---------------- CSR build ----------------
__global__ void k_csr(const int* __restrict__ tgt) {
    __shared__ int cnt[1536];
    __shared__ int buf[1536];
    __shared__ int cur[1536];
    int tid = threadIdx.x;                 // 1024 threads
    for (int i = tid; i < 1536; i += 1024) cnt[i] = 0;
    __syncthreads();
    for (int e = tid; e < NEDGE; e += 1024) atomicAdd(&cnt[tgt[e]], 1);
    __syncthreads();
    int* s_ = cnt; int* d_ = buf;
    for (int off = 1; off < 1536; off <<= 1) {
        for (int i = tid; i < 1536; i += 1024)
            d_[i] = s_[i] + ((i >= off) ? s_[i - off] : 0);
        __syncthreads();
        int* tmp = s_; s_ = d_; d_ = tmp;
    }
    if (tid == 0) g_rowptr[0] = 0;
    for (int i = tid; i < NN; i += 1024) g_rowptr[i + 1] = s_[i];
    for (int i = tid; i < 1536; i += 1024) cur[i] = (i == 0) ? 0 : s_[i - 1];
    __syncthreads();
    for (int e = tid; e < NEDGE; e += 1024) {
        int p = atomicAdd(&cur[tgt[e]], 1);
        g_cols[p] = e;
    }
}

// ---------------- output machinery ----------------
__global__ void k_winner_init() {
    int i = blockIdx.x * blockDim.x + threadIdx.x;
    if (i < NN * NN) g_winner[i] = -1;
}

__global__ void k_winner(const int* __restrict__ src, const int* __restrict__ tgt) {
    int e = blockIdx.x * blockDim.x + threadIdx.x;
    if (e < NEDGE) atomicMax(&g_winner[src[e] * NN + tgt[e]], e);
}

// small-footprint zero pass: 64 blocks only (DRAM-bound; leaves SMs for the loop)
__global__ void __launch_bounds__(512, 1)
k_zero(float4* __restrict__ out4) {
    const int total = NN * NN * (EDIM / 4);
    const float4 z = make_float4(0.f, 0.f, 0.f, 0.f);
    for (int idx = blockIdx.x * blockDim.x + threadIdx.x; idx < total;
         idx += gridDim.x * blockDim.x) {
        int row = idx >> 4;
        if (g_winner[row] < 0) out4[idx] = z;
    }
}

__global__ void k_scatter(const int* __restrict__ src, const int* __restrict__ tgt,
                          float* __restrict__ out) {
    int idx = blockIdx.x * blockDim.x + threadIdx.x;
    if (idx < NEDGE * EDIM) {
        int e = idx >> 6, c = idx & 63;
        int s = src[e], t = tgt[e];
        long long slot = (long long)s * NN + t;
        if (g_winner[slot] == e) out[slot * 64 + c] = g_y[idx];
    }
}

__global__ void k_out_x(float* __restrict__ out) {
    int i = blockIdx.x * blockDim.x + threadIdx.x;
    if (i < NN * EDIM) out[(long long)NN * NN * EDIM + i] = g_x[i];
}

// ---------------- launch ----------------
extern "C" void kernel_launch(void* const* d_in, const int* in_sizes, int n_in,
                              void* d_out, int out_size) {
    const float* v      = (const float*)d_in[0];
    const float* labels = (const float*)d_in[1];
    const int*   ei     = (const int*)d_in[4];
    const float* hx_W1 = (const float*)d_in[6],  *hx_b1 = (const float*)d_in[7];
    const float* hx_W2 = (const float*)d_in[8],  *hx_b2 = (const float*)d_in[9];
    const float* hy_W1 = (const float*)d_in[10], *hy_b1 = (const float*)d_in[11];
    const float* hy_W2 = (const float*)d_in[12], *hy_b2 = (const float*)d_in[13];
    const float* fx_W1 = (const float*)d_in[14], *fx_b1 = (const float*)d_in[15];
    const float* fx_W2 = (const float*)d_in[16], *fx_b2 = (const float*)d_in[17];
    const float* fy_W1 = (const float*)d_in[18], *fy_b1 = (const float*)d_in[19];
    const float* fy_W2 = (const float*)d_in[20], *fy_b2 = (const float*)d_in[21];

    const int* src = ei;
    const int* tgt = ei + NEDGE;
    float* out = (float*)d_out;

    static bool attr_done = false;
    if (!attr_done) {
        cudaFuncSetAttribute(k_fx_edge, cudaFuncAttributeMaxDynamicSharedMemorySize,
                             FX_SM * sizeof(float));
        cudaFuncSetAttribute(k_eyA<0>, cudaFuncAttributeMaxDynamicSharedMemorySize,
                             EYA_SM * sizeof(float));
        cudaFuncSetAttribute(k_eyA<1>, cudaFuncAttributeMaxDynamicSharedMemorySize,
                             EYA_SM * sizeof(float));
        cudaFuncSetAttribute(k_node_B, cudaFuncAttributeMaxDynamicSharedMemorySize,
                             EYA_SM * sizeof(float));
        attr_done = true;
    }

    // low-priority side stream (loop wins scheduling races)
    int prLo = 0, prHi = 0;
    cudaDeviceGetStreamPriorityRange(&prLo, &prHi);   // prLo = least priority (largest value)
    cudaStream_t s2;
    cudaStreamCreateWithPriority(&s2, cudaStreamNonBlocking, prLo);
    cudaEvent_t evFork, evCSR, evJoin;
    cudaEventCreateWithFlags(&evFork, cudaEventDisableTiming);
    cudaEventCreateWithFlags(&evCSR, cudaEventDisableTiming);
    cudaEventCreateWithFlags(&evJoin, cudaEventDisableTiming);

    cudaEventRecord(evFork, 0);

    // main pipeline head — k_fx_edge at submission index 3 for ncu
    k_prep<<<1, 256>>>(v, labels, fx_W1, fy_W1, hy_W1);                        // #0
    k_init<<<NN, 64>>>(hx_W1, hx_b1, hx_W2, hx_b2);                            // #1
    k_eyA<0><<<EB2 + NT2, 512, EYA_SM * sizeof(float)>>>(hy_b1, hy_W2, hy_b2, src, tgt); // #2
    k_fx_edge<<<EB2, 512, FX_SM * sizeof(float)>>>(fx_W1 + 192 * 64, fx_b1, fx_W2, fx_b2, src, tgt); // #3

    // side stream: CSR + winner + small-footprint zero
    cudaStreamWaitEvent(s2, evFork, 0);
    k_csr<<<1, 1024, 0, s2>>>(tgt);
    cudaEventRecord(evCSR, s2);
    k_winner_init<<<(NN * NN + 255) / 256, 256, 0, s2>>>();
    k_winner<<<(NEDGE + 255) / 256, 256, 0, s2>>>(src, tgt);
    k_zero<<<64, 512, 0, s2>>>((float4*)out);
    cudaEventRecord(evJoin, s2);

    // loop: fx_edge -> node_B -> ey+nodeA
    cudaStreamWaitEvent(0, evCSR, 0);
    for (int it = 0; it < LOOPN; it++) {
        if (it > 0)
            k_fx_edge<<<EB2, 512, FX_SM * sizeof(float)>>>(fx_W1 + 192 * 64, fx_b1, fx_W2, fx_b2, src, tgt);
        k_node_B<<<NT2, 512, EYA_SM * sizeof(float)>>>();
        k_eyA<1><<<EB2 + NT2, 512, EYA_SM * sizeof(float)>>>(fy_b1, fy_W2, fy_b2, src, tgt);
    }

    // join side, then outputs
    cudaStreamWaitEvent(0, evJoin, 0);
    k_scatter<<<(NEDGE * EDIM + 255) / 256, 256>>>(src, tgt, out);
    k_out_x<<<(NN * EDIM + 255) / 256, 256>>>(out);
}